// round 10
// baseline (speedup 1.0000x reference)
#include <cuda_runtime.h>
#include <cuda_bf16.h>
#include <cstdint>

// DifferentiableNLMS: B=32, T=2000, F=513, L=32, mu=0.1, eps=1e-8
// Packing change: f32x2 lanes hold TWO INDEPENDENT SEQUENCES
// (seqA=(b,f), seqB=(b+16,f)) so every op is dense-packed and the 16-deep
// ring slides cleanly (slot = t mod 16, compile-time via 8-step blocks with
// alternating phase). 2-way tap split across lane pairs (thread h owns taps
// [16h,16h+16) on an x stream shifted by 16*(1-h); zero-pad makes it exact),
// one shfl64 dot-reduce per step. Incremental packed norm, minv precomputed
// per block off the critical path.

#define NB 32
#define NT 2000
#define NF 513
#define NL 32
#define MU 0.1f
#define EPSV 1e-8f

#define HB 16                  // half batch
#define NSP (HB * NF)          // 8208 sequence-pairs
#define NTHREAD (NSP * 2)      // 16416 threads = 513 full warps
#define NSTEP 8                // steps per block (ring phase alternates 0/8)

typedef unsigned long long u64;

#define NEG1_2 0xBF800000BF800000ULL   // (-1.0f, -1.0f)
#define EPS_2  0x322BCC77322BCC77ULL   // (1e-8f, 1e-8f)

__device__ __forceinline__ u64 ffma2(u64 a, u64 b, u64 c) {
    u64 d; asm("fma.rn.f32x2 %0, %1, %2, %3;" : "=l"(d) : "l"(a), "l"(b), "l"(c));
    return d;
}
__device__ __forceinline__ u64 fadd2(u64 a, u64 b) {
    u64 d; asm("add.rn.f32x2 %0, %1, %2;" : "=l"(d) : "l"(a), "l"(b));
    return d;
}
__device__ __forceinline__ u64 fmul2(u64 a, u64 b) {
    u64 d; asm("mul.rn.f32x2 %0, %1, %2;" : "=l"(d) : "l"(a), "l"(b));
    return d;
}
__device__ __forceinline__ u64 pack2(float lo, float hi) {
    u64 d; asm("mov.b64 %0, {%1, %2};" : "=l"(d) : "f"(lo), "f"(hi));
    return d;
}
__device__ __forceinline__ void unpack2(u64 v, float& lo, float& hi) {
    asm("mov.b64 {%0, %1}, %2;" : "=f"(lo), "=f"(hi) : "l"(v));
}
__device__ __forceinline__ u64 shfl64(u64 v) {
    return __shfl_xor_sync(0xFFFFFFFFu, v, 1);
}

// Prefetch one 8-step block: xA/xB on this thread's shifted stream, yA/yB
// unshifted. Guarded variant for the first two blocks (shifted idx < 0 -> 0).
__device__ __forceinline__ void pf_g(float (&xa)[8], float (&xb)[8],
                                     float (&ya)[8], float (&yb)[8],
                                     const float* xpA, const float* xpB,
                                     const float* ypA, const float* ypB,
                                     int t, int off)
{
#pragma unroll
    for (int u = 0; u < 8; u++) {
        int ti = t + u - off;
        xa[u] = (ti >= 0) ? __ldg(xpA + (size_t)ti * NF) : 0.f;
        xb[u] = (ti >= 0) ? __ldg(xpB + (size_t)ti * NF) : 0.f;
        ya[u] = __ldg(ypA + (size_t)(t + u) * NF);
        yb[u] = __ldg(ypB + (size_t)(t + u) * NF);
    }
}
__device__ __forceinline__ void pf_u(float (&xa)[8], float (&xb)[8],
                                     float (&ya)[8], float (&yb)[8],
                                     const float* xpA, const float* xpB,
                                     const float* ypA, const float* ypB,
                                     int t, int off)
{
#pragma unroll
    for (int u = 0; u < 8; u++) {
        xa[u] = __ldg(xpA + (size_t)(t + u - off) * NF);
        xb[u] = __ldg(xpB + (size_t)(t + u - off) * NF);
        ya[u] = __ldg(ypA + (size_t)(t + u) * NF);
        yb[u] = __ldg(ypB + (size_t)(t + u) * NF);
    }
}

// M0 = ring phase (t0 mod 16): 0 or 8.
template <int M0>
__device__ __forceinline__ void run_block(
    u64 (&W2)[16], u64 (&R2)[16], u64& S2h,
    const float (&xa)[8], const float (&xb)[8],
    const float (&ya)[8], const float (&yb)[8],
    float* __restrict__ epA, float* __restrict__ epB, int t0, int h)
{
    u64 xx[8], minv2[8];
    // ---- Prologue (X-only, off the W chain): packed incremental norm ----
    {
        u64 sp_[8];
#pragma unroll
        for (int u = 0; u < 8; u++) {
            xx[u] = pack2(xa[u], xb[u]);
            u64 o = R2[M0 + u];            // sample dropped at step t0+u
            u64 on = fmul2(o, NEG1_2);
            S2h = ffma2(xx[u], xx[u], S2h);
            S2h = ffma2(on, o, S2h);       // S2h -= o*o
            sp_[u] = S2h;
        }
#pragma unroll
        for (int u = 0; u < 8; u++) {
            u64 ss = fadd2(sp_[u], shfl64(sp_[u]));  // lane-pair sum = full norm
            ss = fadd2(ss, EPS_2);
            float sA, sB;
            unpack2(ss, sA, sB);
            minv2[u] = pack2(__fdividef(MU, sA), __fdividef(MU, sB));
        }
    }
    // ---- Serial recursion: 1 step per iteration, fully packed ----
#pragma unroll
    for (int u = 0; u < 8; u++) {
        R2[M0 + u] = xx[u];                // insert newest (own tap 15)
        // dot over own 16 taps: tap i -> ring slot (M0+u+1+i) & 15
        u64 a0 = 0, a1 = 0, a2 = 0, a3 = 0;
#pragma unroll
        for (int i = 0; i < 16; i += 4) {
            a0 = ffma2(W2[i + 0], R2[(M0 + u + 1 + i) & 15], a0);
            a1 = ffma2(W2[i + 1], R2[(M0 + u + 2 + i) & 15], a1);
            a2 = ffma2(W2[i + 2], R2[(M0 + u + 3 + i) & 15], a2);
            a3 = ffma2(W2[i + 3], R2[(M0 + u + 4 + i) & 15], a3);
        }
        u64 d = fadd2(fadd2(a0, a1), fadd2(a2, a3));
        d = fadd2(d, shfl64(d));           // + other lane's 16 taps
        u64 y2 = pack2(ya[u], yb[u]);
        u64 e2 = ffma2(d, NEG1_2, y2);     // e = y - y_hat (both seqs)
        u64 c2 = fmul2(e2, minv2[u]);

        if (h) {                           // one writer lane per pair
            float eA, eB;
            unpack2(e2, eA, eB);
            epA[(size_t)(t0 + u) * NF] = eA;
            epB[(size_t)(t0 + u) * NF] = eB;
        }
#pragma unroll
        for (int i = 0; i < 16; i++) {
            W2[i] = ffma2(c2, R2[(M0 + u + 1 + i) & 15], W2[i]);
        }
    }
}

__global__ void __launch_bounds__(128, 1)
nlms_kernel(const float* __restrict__ X, const float* __restrict__ Y,
            const float* __restrict__ Wp, float* __restrict__ out,
            int write_w)
{
    int gtid = blockIdx.x * blockDim.x + threadIdx.x;
    if (gtid >= NTHREAD) return;           // whole-warp granularity (513 warps)
    int h = gtid & 1;                      // tap-half owner
    int sp = gtid >> 1;                    // sequence-pair id
    int b = sp / NF;                       // 0..15
    int f = sp - b * NF;
    int off = 16 * (1 - h);                // x-stream time shift

    size_t baseA = (size_t)b * NT * NF + f;
    size_t baseB = (size_t)(b + HB) * NT * NF + f;
    const float* xpA = X + baseA;
    const float* xpB = X + baseB;
    const float* ypA = Y + baseA;
    const float* ypB = Y + baseB;
    float* epA = out + baseA;
    float* epB = out + baseB;

    u64 W2[16], R2[16];
#pragma unroll
    for (int i = 0; i < 16; i++) {
        int j = 16 * h + i;
        float wA = Wp[((size_t)b * NL + j) * NF + f];
        float wB = Wp[((size_t)(b + HB) * NL + j) * NF + f];
        W2[i] = pack2(wA, wB);
        R2[i] = 0;                         // zero pad: window starts empty
    }
    u64 S2h = 0;                           // packed partial norm (own taps)

    float xaA[8], xbA[8], yaA[8], ybA[8];  // buffer A (even blocks, M0=0)
    float xaB[8], xbB[8], yaB[8], ybB[8];  // buffer B (odd blocks,  M0=8)

    pf_g(xaA, xbA, yaA, ybA, xpA, xpB, ypA, ypB, 0, off);   // block 0
    pf_g(xaB, xbB, yaB, ybB, xpA, xpB, ypA, ypB, 8, off);   // block 1

    int t0 = 0;
    // 250 blocks of 8 steps = 125 double-iterations; last has no prefetch.
#pragma unroll 1
    for (int k = 0; k < 124; k++) {
        run_block<0>(W2, R2, S2h, xaA, xbA, yaA, ybA, epA, epB, t0, h);
        pf_u(xaA, xbA, yaA, ybA, xpA, xpB, ypA, ypB, t0 + 16, off);
        run_block<8>(W2, R2, S2h, xaB, xbB, yaB, ybB, epA, epB, t0 + 8, h);
        pf_u(xaB, xbB, yaB, ybB, xpA, xpB, ypA, ypB, t0 + 24, off);
        t0 += 16;
    }
    run_block<0>(W2, R2, S2h, xaA, xbA, yaA, ybA, epA, epB, t0, h);      // 1984
    run_block<8>(W2, R2, S2h, xaB, xbB, yaB, ybB, epA, epB, t0 + 8, h);  // 1992

    if (write_w) {
        float* wf = out + (size_t)NB * NT * NF;   // W_final after E
#pragma unroll
        for (int i = 0; i < 16; i++) {
            int j = 16 * h + i;
            float wA, wB;
            unpack2(W2[i], wA, wB);
            wf[((size_t)b * NL + j) * NF + f] = wA;
            wf[((size_t)(b + HB) * NL + j) * NF + f] = wB;
        }
    }
}

extern "C" void kernel_launch(void* const* d_in, const int* in_sizes, int n_in,
                              void* d_out, int out_size)
{
    const float* X  = (const float*)d_in[0];  // X_hat_mag [B,T,F]
    const float* Y  = (const float*)d_in[1];  // Y_mag     [B,T,F]
    const float* Wp = (const float*)d_in[2];  // W_prev    [B,L,F]
    float* out = (float*)d_out;

    long long need = (long long)NB * NT * NF + (long long)NB * NL * NF;
    int write_w = ((long long)out_size >= need) ? 1 : 0;

    // 16416 threads = 513 full warps; 129 blocks of 128 -> 1 block/SM,
    // exactly 1 warp per SMSP on every active SM (uniform load).
    nlms_kernel<<<129, 128>>>(X, Y, Wp, out, write_w);
}

// round 11
// speedup vs baseline: 1.2785x; 1.2785x over previous
#include <cuda_runtime.h>
#include <cuda_bf16.h>
#include <cstdint>

// DifferentiableNLMS: B=32, T=2000, F=513, L=32, mu=0.1, eps=1e-8
// R5 core (best: 223.9us) with ONE change: no divergent early-exit.
// Excess threads clamp to the last sequence and compute redundantly with
// stores suppressed, so the kernel has zero divergent branches and every
// __shfl_xor_sync site is provably convergent (no WARPSYNC envelopes).
//
// Two threads per (b,f) sequence: thread h owns taps [16h, 16h+16) and runs
// on a time-shifted x stream (h=0 shifted by -16 frames; zero-pad makes this
// exact), so both threads execute identical code on an 8-pair (16-sample)
// ring with compile-time indices. Partial dots/norms/cross-correlations are
// summed with one lane-xor shuffle. Two-step lookahead + packed f32x2 FMAs.

#define NB 32
#define NT 2000
#define NF 513
#define NL 32
#define MU 0.1f
#define EPSV 1e-8f

#define NPAIR (NB * NF)        // 16416 sequences
#define NTHREAD (NPAIR * 2)    // 32832 threads = 1026 full warps
#define NSTEP 16               // steps per block (= one full ring revolution)
#define NPB 8                  // lookahead-pairs per block
#define NDBL 62                // 62*2+1 = 125 blocks = 2000/16

typedef unsigned long long u64;

__device__ __forceinline__ u64 ffma2(u64 a, u64 b, u64 c) {
    u64 d; asm("fma.rn.f32x2 %0, %1, %2, %3;" : "=l"(d) : "l"(a), "l"(b), "l"(c));
    return d;
}
__device__ __forceinline__ u64 fadd2(u64 a, u64 b) {
    u64 d; asm("add.rn.f32x2 %0, %1, %2;" : "=l"(d) : "l"(a), "l"(b));
    return d;
}
__device__ __forceinline__ u64 pack2(float lo, float hi) {
    u64 d; asm("mov.b64 %0, {%1, %2};" : "=l"(d) : "f"(lo), "f"(hi));
    return d;
}
__device__ __forceinline__ void unpack2(u64 v, float& lo, float& hi) {
    asm("mov.b64 {%0, %1}, %2;" : "=f"(lo), "=f"(hi) : "l"(v));
}
__device__ __forceinline__ u64 shfl64(u64 v) {
    return __shfl_xor_sync(0xFFFFFFFFu, v, 1);
}

// Guarded prefetch (first block only: h=0's shifted indices go negative -> 0).
__device__ __forceinline__ void prefetch_g(float (&x)[NSTEP], float (&y)[NSTEP],
                                           const float* __restrict__ xp,
                                           const float* __restrict__ yp,
                                           int t, int off)
{
#pragma unroll
    for (int u = 0; u < NSTEP; u++) {
        int ti = t + u - off;
        x[u] = (ti >= 0) ? __ldg(xp + (size_t)ti * NF) : 0.f;
        y[u] = __ldg(yp + (size_t)(t + u) * NF);
    }
}
// Unguarded prefetch (t >= 16 -> shifted index always in range).
__device__ __forceinline__ void prefetch_u(float (&x)[NSTEP], float (&y)[NSTEP],
                                           const float* __restrict__ xp,
                                           const float* __restrict__ yp,
                                           int t, int off)
{
#pragma unroll
    for (int u = 0; u < NSTEP; u++) {
        x[u] = __ldg(xp + (size_t)(t + u - off) * NF);
        y[u] = __ldg(yp + (size_t)(t + u) * NF);
    }
}

__device__ __forceinline__ void run_block(
    u64 (&W2)[8], u64 (&P)[8], u64 (&Q)[8],
    float& S, float& CC, float& xlast,
    const float (&xb)[NSTEP], const float (&yb)[NSTEP],
    float* __restrict__ ep, int t0, bool writer)
{
    float minv[NSTEP];
    float ccs[NPB];
    float xm1_0 = xlast;

    // ---- Prologue: local partial norms / cross-correlations (X-only) ----
    u64 spp[NPB];
    float cpl[NPB];
    {
        float Sl = S, CCl = CC;
#pragma unroll
        for (int p = 0; p < NPB; p++) {
            float a, b, bq, cq;
            unpack2(P[p], a, b);   // (x'_{t-17}, x'_{t-16})
            unpack2(Q[p], bq, cq); // (x'_{t-16}, x'_{t-15})
            float xm1 = p ? xb[2 * p - 1] : xm1_0;
            float x0 = xb[2 * p], x1 = xb[2 * p + 1];
            Sl = fmaf(x0, x0, Sl);
            Sl = fmaf(-b, b, Sl);
            float s0 = Sl;
            Sl = fmaf(x1, x1, Sl);
            Sl = fmaf(-cq, cq, Sl);
            spp[p] = pack2(s0, Sl);
            CCl = fmaf(xm1, x0, CCl);
            CCl = fmaf(x0, x1, CCl);
            CCl = fmaf(-a, b, CCl);
            CCl = fmaf(-bq, cq, CCl);
            cpl[p] = CCl;
        }
        S = Sl; CC = CCl;
    }
    // Exchange partial norms, compute step sizes (both lanes redundantly).
#pragma unroll
    for (int p = 0; p < NPB; p++) {
        u64 ss = fadd2(spp[p], shfl64(spp[p]));
        float s0, s1;
        unpack2(ss, s0, s1);
        minv[2 * p]     = __fdividef(MU, s0 + EPSV);
        minv[2 * p + 1] = __fdividef(MU, s1 + EPSV);
    }
    // Exchange partial cross-correlations.
#pragma unroll
    for (int p = 0; p < NPB; p += 2) {
        u64 cv = pack2(cpl[p], cpl[p + 1]);
        u64 cs = fadd2(cv, shfl64(cv));
        unpack2(cs, ccs[p], ccs[p + 1]);
    }
    xlast = xb[NSTEP - 1];

    // ---- Serial recursion: 2 steps per iteration ----
#pragma unroll
    for (int p = 0; p < NPB; p++) {
        float xm1 = p ? xb[2 * p - 1] : xm1_0;
        float x0 = xb[2 * p], x1 = xb[2 * p + 1];
        P[p] = pack2(xm1, x0);  // slot holds (x'_{t-1}, x'_t)
        Q[p] = pack2(x0, x1);   // slot holds (x'_t, x'_{t+1})

        // Half-dots over own 8 pair-slots: window pair i -> slot (p+1+i)&7.
        u64 a0 = 0, a1 = 0, a2 = 0, a3 = 0;
        u64 b0 = 0, b1 = 0, b2 = 0, b3 = 0;
#pragma unroll
        for (int i = 0; i < 8; i += 4) {
            a0 = ffma2(W2[i + 0], P[(p + 1 + i) & 7], a0);
            a1 = ffma2(W2[i + 1], P[(p + 2 + i) & 7], a1);
            a2 = ffma2(W2[i + 2], P[(p + 3 + i) & 7], a2);
            a3 = ffma2(W2[i + 3], P[(p + 4 + i) & 7], a3);
            b0 = ffma2(W2[i + 0], Q[(p + 1 + i) & 7], b0);
            b1 = ffma2(W2[i + 1], Q[(p + 2 + i) & 7], b1);
            b2 = ffma2(W2[i + 2], Q[(p + 3 + i) & 7], b2);
            b3 = ffma2(W2[i + 3], Q[(p + 4 + i) & 7], b3);
        }
        u64 ap = fadd2(fadd2(a0, a1), fadd2(a2, a3));
        u64 aq = fadd2(fadd2(b0, b1), fadd2(b2, b3));
        float plo, phi, qlo, qhi;
        unpack2(ap, plo, phi);
        unpack2(aq, qlo, qhi);
        // Sum halves across the lane pair with one 64-bit butterfly.
        u64 pq = pack2(plo + phi, qlo + qhi);
        u64 pqs = fadd2(pq, shfl64(pq));
        float pt, qt;
        unpack2(pqs, pt, qt);

        float e0 = yb[2 * p] - pt;
        float c0 = e0 * minv[2 * p];
        float e1 = fmaf(-c0, ccs[p], yb[2 * p + 1] - qt);
        float c1 = e1 * minv[2 * p + 1];

        if (writer) {  // predicated stores; no divergence impact on shuffles
            ep[(size_t)(t0 + 2 * p) * NF] = e0;
            ep[(size_t)(t0 + 2 * p + 1) * NF] = e1;
        }

        u64 c0p = pack2(c0, c0);
        u64 c1p = pack2(c1, c1);
#pragma unroll
        for (int i = 0; i < 8; i++) {
            W2[i] = ffma2(c1p, Q[(p + 1 + i) & 7],
                          ffma2(c0p, P[(p + 1 + i) & 7], W2[i]));
        }
    }
}

__global__ void __launch_bounds__(128, 2)
nlms_kernel(const float* __restrict__ X, const float* __restrict__ Y,
            const float* __restrict__ Wp, float* __restrict__ out,
            int write_w)
{
    int gtid = blockIdx.x * blockDim.x + threadIdx.x;
    // NO divergent exit: clamp out-of-range threads onto the last sequence
    // slot and suppress their stores. Keeps every warp fully convergent so
    // ptxas can prove convergence at all shuffle sites.
    bool valid = (gtid < NTHREAD);
    int g = valid ? gtid : (NTHREAD - 1);
    int h = g & 1;             // tap-half owner
    int seq = g >> 1;
    int b = seq / NF;
    int f = seq - b * NF;
    int off = 16 * (1 - h);    // time shift of this thread's x stream

    size_t base = (size_t)b * NT * NF + f;
    const float* xp = X + base;
    const float* yp = Y + base;
    float* ep = out + base;    // E_hat_mag at offset 0
    bool writer = (h == 1) && valid;

    u64 W2[8], P[8], Q[8];
#pragma unroll
    for (int i = 0; i < 8; i++) {
        int j = 16 * h + 2 * i;
        float w0 = Wp[((size_t)b * NL + j) * NF + f];
        float w1 = Wp[((size_t)b * NL + j + 1) * NF + f];
        W2[i] = pack2(w0, w1);
        P[i] = 0;  // zero pad: window starts empty
        Q[i] = 0;
    }
    float S = 0.f, CC = 0.f, xlast = 0.f;

    float xA[NSTEP], yA[NSTEP], xB[NSTEP], yB[NSTEP];
    prefetch_g(xA, yA, xp, yp, 0, off);

    int t0 = 0;
#pragma unroll 1
    for (int dd = 0; dd < NDBL; dd++) {
        prefetch_u(xB, yB, xp, yp, t0 + NSTEP, off);
        run_block(W2, P, Q, S, CC, xlast, xA, yA, ep, t0, writer);
        t0 += NSTEP;
        prefetch_u(xA, yA, xp, yp, t0 + NSTEP, off);  // last lands on block 124
        run_block(W2, P, Q, S, CC, xlast, xB, yB, ep, t0, writer);
        t0 += NSTEP;
    }
    run_block(W2, P, Q, S, CC, xlast, xA, yA, ep, t0, writer);  // t0 = 1984

    if (write_w) {
        float* wf = out + (size_t)NB * NT * NF;  // W_final after E
#pragma unroll
        for (int i = 0; i < 8; i++) {
            int j = 16 * h + 2 * i;
            float w0, w1;
            unpack2(W2[i], w0, w1);
            if (valid) {
                wf[((size_t)b * NL + j) * NF + f] = w0;
                wf[((size_t)b * NL + j + 1) * NF + f] = w1;
            }
        }
    }
}

extern "C" void kernel_launch(void* const* d_in, const int* in_sizes, int n_in,
                              void* d_out, int out_size)
{
    const float* X  = (const float*)d_in[0];  // X_hat_mag [B,T,F]
    const float* Y  = (const float*)d_in[1];  // Y_mag     [B,T,F]
    const float* Wp = (const float*)d_in[2];  // W_prev    [B,L,F]
    float* out = (float*)d_out;

    long long need = (long long)NB * NT * NF + (long long)NB * NL * NF;
    int write_w = ((long long)out_size >= need) ? 1 : 0;

    // 32832 live threads (1026 warps) + 64 clamped duplicates; 257 blocks.
    nlms_kernel<<<257, 128>>>(X, Y, Wp, out, write_w);
}

// round 12
// speedup vs baseline: 1.3883x; 1.0859x over previous
#include <cuda_runtime.h>
#include <cuda_bf16.h>
#include <cstdint>

// DifferentiableNLMS: B=32, T=2000, F=513, L=32, mu=0.1, eps=1e-8
// R5 core + fma-pipe diet:
//  - packed (S,CC) prologue chain (ffma2 instead of scalar fmaf)
//  - EPS folded into S's initial value (one lane) - no per-step eps add
//  - scalar float shuffle exchanges (no pack/unpack around SHFL)
//  - 4-accumulator dot (fewer fadd2 in the reduce tree)
// Two threads per (b,f): thread h owns taps [16h,16h+16) on an x stream
// shifted by 16*(1-h) (zero-pad makes it exact). Two-step lookahead.

#define NB 32
#define NT 2000
#define NF 513
#define NL 32
#define MU 0.1f
#define EPSV 1e-8f

#define NPAIR (NB * NF)        // 16416 sequences
#define NTHREAD (NPAIR * 2)    // 32832 threads = 1026 full warps
#define NSTEP 16
#define NPB 8
#define NDBL 62                // 62*2+1 = 125 blocks

typedef unsigned long long u64;

__device__ __forceinline__ u64 ffma2(u64 a, u64 b, u64 c) {
    u64 d; asm("fma.rn.f32x2 %0, %1, %2, %3;" : "=l"(d) : "l"(a), "l"(b), "l"(c));
    return d;
}
__device__ __forceinline__ u64 fadd2(u64 a, u64 b) {
    u64 d; asm("add.rn.f32x2 %0, %1, %2;" : "=l"(d) : "l"(a), "l"(b));
    return d;
}
__device__ __forceinline__ u64 pack2(float lo, float hi) {
    u64 d; asm("mov.b64 %0, {%1, %2};" : "=l"(d) : "f"(lo), "f"(hi));
    return d;
}
__device__ __forceinline__ void unpack2(u64 v, float& lo, float& hi) {
    asm("mov.b64 {%0, %1}, %2;" : "=f"(lo), "=f"(hi) : "l"(v));
}
__device__ __forceinline__ u64 shfl64(u64 v) {
    return __shfl_xor_sync(0xFFFFFFFFu, v, 1);
}
__device__ __forceinline__ float shflf(float v) {
    return __shfl_xor_sync(0xFFFFFFFFu, v, 1);
}
__device__ __forceinline__ float negf(float x) {   // sign flip on alu pipe
    return __int_as_float(__float_as_int(x) ^ 0x80000000);
}

__device__ __forceinline__ void prefetch_g(float (&x)[NSTEP], float (&y)[NSTEP],
                                           const float* __restrict__ xp,
                                           const float* __restrict__ yp,
                                           int t, int off)
{
#pragma unroll
    for (int u = 0; u < NSTEP; u++) {
        int ti = t + u - off;
        x[u] = (ti >= 0) ? __ldg(xp + (size_t)ti * NF) : 0.f;
        y[u] = __ldg(yp + (size_t)(t + u) * NF);
    }
}
__device__ __forceinline__ void prefetch_u(float (&x)[NSTEP], float (&y)[NSTEP],
                                           const float* __restrict__ xp,
                                           const float* __restrict__ yp,
                                           int t, int off)
{
#pragma unroll
    for (int u = 0; u < NSTEP; u++) {
        x[u] = __ldg(xp + (size_t)(t + u - off) * NF);
        y[u] = __ldg(yp + (size_t)(t + u) * NF);
    }
}

__device__ __forceinline__ void run_block(
    u64 (&W2)[8], u64 (&P)[8], u64 (&Q)[8],
    u64& SC, float& xlast,
    const float (&xb)[NSTEP], const float (&yb)[NSTEP],
    float* __restrict__ ep, int t0, bool writer)
{
    float minv[NSTEP];
    float ccs[NPB];
    float xm1_0 = xlast;

    // ---- Prologue: packed (S | CC) incremental chain, X-only ----
    // lo(SC) = running full-window norm partial (own 16 taps, +EPS in lane 1)
    // hi(SC) = running lag-1 cross-correlation partial
    float s0a[NPB], s1a[NPB], cca[NPB];
    {
        u64 sc = SC;
#pragma unroll
        for (int p = 0; p < NPB; p++) {
            float a, b, bq, cq;
            unpack2(P[p], a, b);   // (x'_{t-17}, x'_{t-16})
            unpack2(Q[p], bq, cq); // (x'_{t-16}, x'_{t-15})
            float xm1 = p ? xb[2 * p - 1] : xm1_0;
            float x0 = xb[2 * p], x1 = xb[2 * p + 1];
            // S += x0^2 ; CC += xm1*x0
            sc = ffma2(pack2(x0, xm1), pack2(x0, x0), sc);
            // S -= b^2  ; CC -= a*b
            sc = ffma2(pack2(negf(b), negf(a)), pack2(b, b), sc);
            { float slo, shi; unpack2(sc, slo, shi); s0a[p] = slo; }
            // S += x1^2 ; CC += x0*x1
            sc = ffma2(pack2(x1, x0), pack2(x1, x1), sc);
            // S -= cq^2 ; CC -= bq*cq
            sc = ffma2(pack2(negf(cq), negf(bq)), pack2(cq, cq), sc);
            { float slo, shi; unpack2(sc, slo, shi); s1a[p] = slo; cca[p] = shi; }
        }
        SC = sc;
    }
    // Lane-pair sums (scalar shuffles) + step sizes. EPS already inside S.
#pragma unroll
    for (int p = 0; p < NPB; p++) {
        float s0f = s0a[p] + shflf(s0a[p]);
        float s1f = s1a[p] + shflf(s1a[p]);
        minv[2 * p]     = __fdividef(MU, s0f);
        minv[2 * p + 1] = __fdividef(MU, s1f);
    }
#pragma unroll
    for (int p = 0; p < NPB; p++) {
        ccs[p] = cca[p] + shflf(cca[p]);
    }
    xlast = xb[NSTEP - 1];

    // ---- Serial recursion: 2 steps per iteration ----
#pragma unroll
    for (int p = 0; p < NPB; p++) {
        float xm1 = p ? xb[2 * p - 1] : xm1_0;
        float x0 = xb[2 * p], x1 = xb[2 * p + 1];
        P[p] = pack2(xm1, x0);
        Q[p] = pack2(x0, x1);

        // Half-dots, 4 accumulators (2 per phase).
        u64 a0 = 0, a1 = 0, b0 = 0, b1 = 0;
#pragma unroll
        for (int i = 0; i < 8; i += 2) {
            a0 = ffma2(W2[i],     P[(p + 1 + i) & 7], a0);
            a1 = ffma2(W2[i + 1], P[(p + 2 + i) & 7], a1);
            b0 = ffma2(W2[i],     Q[(p + 1 + i) & 7], b0);
            b1 = ffma2(W2[i + 1], Q[(p + 2 + i) & 7], b1);
        }
        u64 ap = fadd2(a0, a1);
        u64 aq = fadd2(b0, b1);
        float plo, phi, qlo, qhi;
        unpack2(ap, plo, phi);
        unpack2(aq, qlo, qhi);
        u64 pq = pack2(plo + phi, qlo + qhi);
        u64 pqs = fadd2(pq, shfl64(pq));   // one latency stage, both dots
        float pt, qt;
        unpack2(pqs, pt, qt);

        float e0 = yb[2 * p] - pt;
        float c0 = e0 * minv[2 * p];
        float e1 = fmaf(-c0, ccs[p], yb[2 * p + 1] - qt);
        float c1 = e1 * minv[2 * p + 1];

        if (writer) {
            ep[(size_t)(t0 + 2 * p) * NF] = e0;
            ep[(size_t)(t0 + 2 * p + 1) * NF] = e1;
        }

        u64 c0p = pack2(c0, c0);
        u64 c1p = pack2(c1, c1);
#pragma unroll
        for (int i = 0; i < 8; i++) {
            W2[i] = ffma2(c1p, Q[(p + 1 + i) & 7],
                          ffma2(c0p, P[(p + 1 + i) & 7], W2[i]));
        }
    }
}

__global__ void __launch_bounds__(128, 2)
nlms_kernel(const float* __restrict__ X, const float* __restrict__ Y,
            const float* __restrict__ Wp, float* __restrict__ out,
            int write_w)
{
    int gtid = blockIdx.x * blockDim.x + threadIdx.x;
    bool valid = (gtid < NTHREAD);
    int g = valid ? gtid : (NTHREAD - 1);   // clamp: no divergent exit
    int h = g & 1;
    int seq = g >> 1;
    int b = seq / NF;
    int f = seq - b * NF;
    int off = 16 * (1 - h);

    size_t base = (size_t)b * NT * NF + f;
    const float* xp = X + base;
    const float* yp = Y + base;
    float* ep = out + base;
    bool writer = (h == 1) && valid;

    u64 W2[8], P[8], Q[8];
#pragma unroll
    for (int i = 0; i < 8; i++) {
        int j = 16 * h + 2 * i;
        float w0 = Wp[((size_t)b * NL + j) * NF + f];
        float w1 = Wp[((size_t)b * NL + j + 1) * NF + f];
        W2[i] = pack2(w0, w1);
        P[i] = 0;
        Q[i] = 0;
    }
    // lo = norm partial (lane 1 seeds EPS so the pair-sum carries exactly one
    // EPS), hi = lag-1 cross-correlation partial.
    u64 SC = pack2(h ? EPSV : 0.f, 0.f);
    float xlast = 0.f;

    float xA[NSTEP], yA[NSTEP], xB[NSTEP], yB[NSTEP];
    prefetch_g(xA, yA, xp, yp, 0, off);

    int t0 = 0;
#pragma unroll 1
    for (int dd = 0; dd < NDBL; dd++) {
        prefetch_u(xB, yB, xp, yp, t0 + NSTEP, off);
        run_block(W2, P, Q, SC, xlast, xA, yA, ep, t0, writer);
        t0 += NSTEP;
        prefetch_u(xA, yA, xp, yp, t0 + NSTEP, off);  // last lands on block 124
        run_block(W2, P, Q, SC, xlast, xB, yB, ep, t0, writer);
        t0 += NSTEP;
    }
    run_block(W2, P, Q, SC, xlast, xA, yA, ep, t0, writer);  // t0 = 1984

    if (write_w) {
        float* wf = out + (size_t)NB * NT * NF;
#pragma unroll
        for (int i = 0; i < 8; i++) {
            int j = 16 * h + 2 * i;
            float w0, w1;
            unpack2(W2[i], w0, w1);
            if (valid) {
                wf[((size_t)b * NL + j) * NF + f] = w0;
                wf[((size_t)b * NL + j + 1) * NF + f] = w1;
            }
        }
    }
}

extern "C" void kernel_launch(void* const* d_in, const int* in_sizes, int n_in,
                              void* d_out, int out_size)
{
    const float* X  = (const float*)d_in[0];  // X_hat_mag [B,T,F]
    const float* Y  = (const float*)d_in[1];  // Y_mag     [B,T,F]
    const float* Wp = (const float*)d_in[2];  // W_prev    [B,L,F]
    float* out = (float*)d_out;

    long long need = (long long)NB * NT * NF + (long long)NB * NL * NF;
    int write_w = ((long long)out_size >= need) ? 1 : 0;

    nlms_kernel<<<257, 128>>>(X, Y, Wp, out, write_w);
}